// round 13
// baseline (speedup 1.0000x reference)
#include <cuda_runtime.h>

// Pixel-wise diagonal RNN:
//   h_t = leaky_relu(W_ih * x_t + W_hh * h_{t-1} + b_hh), h_0 = 0
// Streaming-bound. R10 winner: 133.2us @ DRAM 78.4%, regs=59, 4 blocks/SM
// (592 slots, grid 1024 -> 1.73 waves). Two MLP probes (R6 reg-batching,
// R11 cp.async pipeline) both REGRESSED -> in-flight bytes are not the
// limiter. This round probes the occupancy/tail axis: force 5 blocks/SM
// via launch_bounds(256,5) (caps regs at 51) -> 740 slots, 1.38 waves,
// +25% resident warps.

#ifndef NEG_SLOPE
#define NEG_SLOPE 0.01f
#endif

__global__ __launch_bounds__(256, 5) void pixelwise_rnn_kernel(
    const float4* __restrict__ x,     // (T, P/4)
    const float4* __restrict__ w_ih,  // (P/4)
    const float4* __restrict__ w_hh,  // (P/4)
    const float4* __restrict__ b_hh,  // (P/4)
    float4* __restrict__ out,         // (T, P/4)
    int P4, int T)
{
    // each thread owns two adjacent float4s: indices 2*tid, 2*tid+1
    int p = 2 * (blockIdx.x * blockDim.x + threadIdx.x);

    const float4 wi0 = w_ih[p],   wi1 = w_ih[p + 1];
    const float4 wh0 = w_hh[p],   wh1 = w_hh[p + 1];
    const float4 b0  = b_hh[p],   b1  = b_hh[p + 1];

    float4 h0 = make_float4(0.f, 0.f, 0.f, 0.f);
    float4 h1 = make_float4(0.f, 0.f, 0.f, 0.f);

    const float4* xp = x + p;
    float4* op = out + p;

    #pragma unroll 5
    for (int t = 0; t < T; ++t) {
        size_t off = (size_t)t * P4;
        float4 xv0 = __ldcs(xp + off);
        float4 xv1 = __ldcs(xp + off + 1);

        float4 v0, v1;
        v0.x = fmaf(wi0.x, xv0.x, fmaf(wh0.x, h0.x, b0.x));
        v0.y = fmaf(wi0.y, xv0.y, fmaf(wh0.y, h0.y, b0.y));
        v0.z = fmaf(wi0.z, xv0.z, fmaf(wh0.z, h0.z, b0.z));
        v0.w = fmaf(wi0.w, xv0.w, fmaf(wh0.w, h0.w, b0.w));
        v1.x = fmaf(wi1.x, xv1.x, fmaf(wh1.x, h1.x, b1.x));
        v1.y = fmaf(wi1.y, xv1.y, fmaf(wh1.y, h1.y, b1.y));
        v1.z = fmaf(wi1.z, xv1.z, fmaf(wh1.z, h1.z, b1.z));
        v1.w = fmaf(wi1.w, xv1.w, fmaf(wh1.w, h1.w, b1.w));

        // leaky_relu with slope in (0,1): max(v, slope*v)
        h0.x = fmaxf(v0.x, NEG_SLOPE * v0.x);
        h0.y = fmaxf(v0.y, NEG_SLOPE * v0.y);
        h0.z = fmaxf(v0.z, NEG_SLOPE * v0.z);
        h0.w = fmaxf(v0.w, NEG_SLOPE * v0.w);
        h1.x = fmaxf(v1.x, NEG_SLOPE * v1.x);
        h1.y = fmaxf(v1.y, NEG_SLOPE * v1.y);
        h1.z = fmaxf(v1.z, NEG_SLOPE * v1.z);
        h1.w = fmaxf(v1.w, NEG_SLOPE * v1.w);

        __stcs(op + off,     h0);
        __stcs(op + off + 1, h1);
    }
}

extern "C" void kernel_launch(void* const* d_in, const int* in_sizes, int n_in,
                              void* d_out, int out_size)
{
    const float* x    = (const float*)d_in[0];  // (B=1, T, Z, H, W)
    const float* w_ih = (const float*)d_in[1];  // (Z, H, W)
    const float* w_hh = (const float*)d_in[2];
    const float* b_hh = (const float*)d_in[3];
    float* out = (float*)d_out;

    int P = in_sizes[1];            // Z*H*W = 2097152
    int T = in_sizes[0] / P;        // 50
    int P4 = P / 4;                 // 524288

    int threads = 256;
    int pairs = P4 / 2;             // 262144 threads, 2 float4 each
    int blocks = (pairs + threads - 1) / threads;
    pixelwise_rnn_kernel<<<blocks, threads>>>(
        (const float4*)x, (const float4*)w_ih, (const float4*)w_hh,
        (const float4*)b_hh, (float4*)out, P4, T);
}

// round 14
// speedup vs baseline: 1.1752x; 1.1752x over previous
#include <cuda_runtime.h>

// Pixel-wise diagonal RNN:
//   h_t = leaky_relu(W_ih * x_t + W_hh * h_{t-1} + b_hh), h_0 = 0
// Streaming-bound. R10 winner: 133.2us @ DRAM 78.4% (2 adjacent float4 per
// thread -> each LDG/STG.128 has lanes 32B apart: 8-line span, half-filled
// sectors, partial-sector STORES). This round: identical body/schedule but
// thread owns base+tid and base+tid+256 -> every memory instruction is a
// fully-coalesced 512B warp access (4 lines, all sectors full).
// MLP probes (R6 reg, R11 smem) and occupancy probe (R13) all regressed;
// do not touch those axes.

#ifndef NEG_SLOPE
#define NEG_SLOPE 0.01f
#endif

__global__ __launch_bounds__(256) void pixelwise_rnn_kernel(
    const float4* __restrict__ x,     // (T, P/4)
    const float4* __restrict__ w_ih,  // (P/4)
    const float4* __restrict__ w_hh,  // (P/4)
    const float4* __restrict__ b_hh,  // (P/4)
    float4* __restrict__ out,         // (T, P/4)
    int P4, int T)
{
    // block owns 512 contiguous float4s; thread owns tid and tid+256
    int tid = threadIdx.x;
    int q0 = blockIdx.x * 512 + tid;
    int q1 = q0 + 256;

    const float4 wi0 = w_ih[q0], wi1 = w_ih[q1];
    const float4 wh0 = w_hh[q0], wh1 = w_hh[q1];
    const float4 b0  = b_hh[q0], b1  = b_hh[q1];

    float4 h0 = make_float4(0.f, 0.f, 0.f, 0.f);
    float4 h1 = make_float4(0.f, 0.f, 0.f, 0.f);

    const float4* xp0 = x + q0;
    const float4* xp1 = x + q1;
    float4* op0 = out + q0;
    float4* op1 = out + q1;

    #pragma unroll 5
    for (int t = 0; t < T; ++t) {
        size_t off = (size_t)t * P4;
        float4 xv0 = __ldcs(xp0 + off);
        float4 xv1 = __ldcs(xp1 + off);

        float4 v0, v1;
        v0.x = fmaf(wi0.x, xv0.x, fmaf(wh0.x, h0.x, b0.x));
        v0.y = fmaf(wi0.y, xv0.y, fmaf(wh0.y, h0.y, b0.y));
        v0.z = fmaf(wi0.z, xv0.z, fmaf(wh0.z, h0.z, b0.z));
        v0.w = fmaf(wi0.w, xv0.w, fmaf(wh0.w, h0.w, b0.w));
        v1.x = fmaf(wi1.x, xv1.x, fmaf(wh1.x, h1.x, b1.x));
        v1.y = fmaf(wi1.y, xv1.y, fmaf(wh1.y, h1.y, b1.y));
        v1.z = fmaf(wi1.z, xv1.z, fmaf(wh1.z, h1.z, b1.z));
        v1.w = fmaf(wi1.w, xv1.w, fmaf(wh1.w, h1.w, b1.w));

        // leaky_relu with slope in (0,1): max(v, slope*v)
        h0.x = fmaxf(v0.x, NEG_SLOPE * v0.x);
        h0.y = fmaxf(v0.y, NEG_SLOPE * v0.y);
        h0.z = fmaxf(v0.z, NEG_SLOPE * v0.z);
        h0.w = fmaxf(v0.w, NEG_SLOPE * v0.w);
        h1.x = fmaxf(v1.x, NEG_SLOPE * v1.x);
        h1.y = fmaxf(v1.y, NEG_SLOPE * v1.y);
        h1.z = fmaxf(v1.z, NEG_SLOPE * v1.z);
        h1.w = fmaxf(v1.w, NEG_SLOPE * v1.w);

        __stcs(op0 + off, h0);
        __stcs(op1 + off, h1);
    }
}

extern "C" void kernel_launch(void* const* d_in, const int* in_sizes, int n_in,
                              void* d_out, int out_size)
{
    const float* x    = (const float*)d_in[0];  // (B=1, T, Z, H, W)
    const float* w_ih = (const float*)d_in[1];  // (Z, H, W)
    const float* w_hh = (const float*)d_in[2];
    const float* b_hh = (const float*)d_in[3];
    float* out = (float*)d_out;

    int P = in_sizes[1];            // Z*H*W = 2097152
    int T = in_sizes[0] / P;        // 50
    int P4 = P / 4;                 // 524288

    int threads = 256;
    int blocks = P4 / 512;          // 1024 blocks, 512 float4 per block
    pixelwise_rnn_kernel<<<blocks, threads>>>(
        (const float4*)x, (const float4*)w_ih, (const float4*)w_hh,
        (const float4*)b_hh, (float4*)out, P4, T);
}

// round 15
// speedup vs baseline: 1.2037x; 1.0242x over previous
#include <cuda_runtime.h>

// Pixel-wise diagonal RNN:
//   h_t = leaky_relu(W_ih * x_t + W_hh * h_{t-1} + b_hh), h_0 = 0
// Streaming-bound. R10 winner: 133.2us @ DRAM 78.4% — adjacent-pair float4
// layout, unroll 5, __ldcs/__stcs. All demand-side probes (R6 regs, R11
// cp.async, R13 occupancy, R14 sector layout) regressed.
// This round: identical layout/math, but use sm_100+ 256-bit global
// accesses (ld/st.global.v8.f32) — one LDG.256 + one STG.256 per timestep
// per thread instead of 2x128-bit each. Halves memory instruction count,
// 1024B fully-coalesced warp requests.

#ifndef NEG_SLOPE
#define NEG_SLOPE 0.01f
#endif

struct __align__(32) f8 { float4 a, b; };

__device__ __forceinline__ f8 ldg256_cs(const f8* p) {
    f8 r;
    asm volatile("ld.global.cs.v8.f32 {%0,%1,%2,%3,%4,%5,%6,%7}, [%8];"
                 : "=f"(r.a.x), "=f"(r.a.y), "=f"(r.a.z), "=f"(r.a.w),
                   "=f"(r.b.x), "=f"(r.b.y), "=f"(r.b.z), "=f"(r.b.w)
                 : "l"(p));
    return r;
}

__device__ __forceinline__ void stg256_cs(f8* p, const f8& v) {
    asm volatile("st.global.cs.v8.f32 [%0], {%1,%2,%3,%4,%5,%6,%7,%8};"
                 :: "l"(p),
                    "f"(v.a.x), "f"(v.a.y), "f"(v.a.z), "f"(v.a.w),
                    "f"(v.b.x), "f"(v.b.y), "f"(v.b.z), "f"(v.b.w)
                 : "memory");
}

__global__ __launch_bounds__(256) void pixelwise_rnn_kernel(
    const f8* __restrict__ x,     // (T, P/8)
    const f8* __restrict__ w_ih,  // (P/8)
    const f8* __restrict__ w_hh,  // (P/8)
    const f8* __restrict__ b_hh,  // (P/8)
    f8* __restrict__ out,         // (T, P/8)
    int P8, int T)
{
    int p = blockIdx.x * blockDim.x + threadIdx.x;   // one f8 (8 pixels)

    const f8 wi = w_ih[p];
    const f8 wh = w_hh[p];
    const f8 b  = b_hh[p];

    f8 h;
    h.a = make_float4(0.f, 0.f, 0.f, 0.f);
    h.b = make_float4(0.f, 0.f, 0.f, 0.f);

    const f8* xp = x + p;
    f8* op = out + p;

    #pragma unroll 5
    for (int t = 0; t < T; ++t) {
        size_t off = (size_t)t * P8;
        f8 xv = ldg256_cs(xp + off);

        float4 v0, v1;
        v0.x = fmaf(wi.a.x, xv.a.x, fmaf(wh.a.x, h.a.x, b.a.x));
        v0.y = fmaf(wi.a.y, xv.a.y, fmaf(wh.a.y, h.a.y, b.a.y));
        v0.z = fmaf(wi.a.z, xv.a.z, fmaf(wh.a.z, h.a.z, b.a.z));
        v0.w = fmaf(wi.a.w, xv.a.w, fmaf(wh.a.w, h.a.w, b.a.w));
        v1.x = fmaf(wi.b.x, xv.b.x, fmaf(wh.b.x, h.b.x, b.b.x));
        v1.y = fmaf(wi.b.y, xv.b.y, fmaf(wh.b.y, h.b.y, b.b.y));
        v1.z = fmaf(wi.b.z, xv.b.z, fmaf(wh.b.z, h.b.z, b.b.z));
        v1.w = fmaf(wi.b.w, xv.b.w, fmaf(wh.b.w, h.b.w, b.b.w));

        // leaky_relu with slope in (0,1): max(v, slope*v)
        h.a.x = fmaxf(v0.x, NEG_SLOPE * v0.x);
        h.a.y = fmaxf(v0.y, NEG_SLOPE * v0.y);
        h.a.z = fmaxf(v0.z, NEG_SLOPE * v0.z);
        h.a.w = fmaxf(v0.w, NEG_SLOPE * v0.w);
        h.b.x = fmaxf(v1.x, NEG_SLOPE * v1.x);
        h.b.y = fmaxf(v1.y, NEG_SLOPE * v1.y);
        h.b.z = fmaxf(v1.z, NEG_SLOPE * v1.z);
        h.b.w = fmaxf(v1.w, NEG_SLOPE * v1.w);

        stg256_cs(op + off, h);
    }
}

extern "C" void kernel_launch(void* const* d_in, const int* in_sizes, int n_in,
                              void* d_out, int out_size)
{
    const float* x    = (const float*)d_in[0];  // (B=1, T, Z, H, W)
    const float* w_ih = (const float*)d_in[1];  // (Z, H, W)
    const float* w_hh = (const float*)d_in[2];
    const float* b_hh = (const float*)d_in[3];
    float* out = (float*)d_out;

    int P = in_sizes[1];            // Z*H*W = 2097152
    int T = in_sizes[0] / P;        // 50
    int P8 = P / 8;                 // 262144

    int threads = 256;
    int blocks = P8 / threads;      // 1024 blocks, one f8 per thread
    pixelwise_rnn_kernel<<<blocks, threads>>>(
        (const f8*)x, (const f8*)w_ih, (const f8*)w_hh,
        (const f8*)b_hh, (f8*)out, P8, T);
}

// round 16
// speedup vs baseline: 1.2230x; 1.0160x over previous
#include <cuda_runtime.h>

// Pixel-wise diagonal RNN:
//   h_t = leaky_relu(W_ih * x_t + W_hh * h_{t-1} + b_hh), h_0 = 0
// Streaming-bound. R15: v8 256-bit ld/st -> ncu 129.0us, DRAM 80.0%
// (= LTS cap ~6300 B/cyc). This round: fix the 1.73-wave raggedness.
// Launch 512 CTAs (single wave, 592 slots available), each CTA runs TWO
// chunks sequentially (bid, bid+512) -> perfectly balanced, no wave
// transition, identical total traffic. Outer loop unroll-forbidden so the
// two chunks cannot be interleaved (register blowup, see R6).

#ifndef NEG_SLOPE
#define NEG_SLOPE 0.01f
#endif

struct __align__(32) f8 { float4 a, b; };

__device__ __forceinline__ f8 ldg256_cs(const f8* p) {
    f8 r;
    asm volatile("ld.global.cs.v8.f32 {%0,%1,%2,%3,%4,%5,%6,%7}, [%8];"
                 : "=f"(r.a.x), "=f"(r.a.y), "=f"(r.a.z), "=f"(r.a.w),
                   "=f"(r.b.x), "=f"(r.b.y), "=f"(r.b.z), "=f"(r.b.w)
                 : "l"(p));
    return r;
}

__device__ __forceinline__ void stg256_cs(f8* p, const f8& v) {
    asm volatile("st.global.cs.v8.f32 [%0], {%1,%2,%3,%4,%5,%6,%7,%8};"
                 :: "l"(p),
                    "f"(v.a.x), "f"(v.a.y), "f"(v.a.z), "f"(v.a.w),
                    "f"(v.b.x), "f"(v.b.y), "f"(v.b.z), "f"(v.b.w)
                 : "memory");
}

__global__ __launch_bounds__(256) void pixelwise_rnn_kernel(
    const f8* __restrict__ x,     // (T, P/8)
    const f8* __restrict__ w_ih,  // (P/8)
    const f8* __restrict__ w_hh,  // (P/8)
    const f8* __restrict__ b_hh,  // (P/8)
    f8* __restrict__ out,         // (T, P/8)
    int P8, int T, int nblocks)
{
    #pragma unroll 1
    for (int c = 0; c < 2; ++c) {
        int p = (blockIdx.x + c * nblocks) * blockDim.x + threadIdx.x;

        const f8 wi = w_ih[p];
        const f8 wh = w_hh[p];
        const f8 b  = b_hh[p];

        f8 h;
        h.a = make_float4(0.f, 0.f, 0.f, 0.f);
        h.b = make_float4(0.f, 0.f, 0.f, 0.f);

        const f8* xp = x + p;
        f8* op = out + p;

        #pragma unroll 5
        for (int t = 0; t < T; ++t) {
            size_t off = (size_t)t * P8;
            f8 xv = ldg256_cs(xp + off);

            float4 v0, v1;
            v0.x = fmaf(wi.a.x, xv.a.x, fmaf(wh.a.x, h.a.x, b.a.x));
            v0.y = fmaf(wi.a.y, xv.a.y, fmaf(wh.a.y, h.a.y, b.a.y));
            v0.z = fmaf(wi.a.z, xv.a.z, fmaf(wh.a.z, h.a.z, b.a.z));
            v0.w = fmaf(wi.a.w, xv.a.w, fmaf(wh.a.w, h.a.w, b.a.w));
            v1.x = fmaf(wi.b.x, xv.b.x, fmaf(wh.b.x, h.b.x, b.b.x));
            v1.y = fmaf(wi.b.y, xv.b.y, fmaf(wh.b.y, h.b.y, b.b.y));
            v1.z = fmaf(wi.b.z, xv.b.z, fmaf(wh.b.z, h.b.z, b.b.z));
            v1.w = fmaf(wi.b.w, xv.b.w, fmaf(wh.b.w, h.b.w, b.b.w));

            // leaky_relu with slope in (0,1): max(v, slope*v)
            h.a.x = fmaxf(v0.x, NEG_SLOPE * v0.x);
            h.a.y = fmaxf(v0.y, NEG_SLOPE * v0.y);
            h.a.z = fmaxf(v0.z, NEG_SLOPE * v0.z);
            h.a.w = fmaxf(v0.w, NEG_SLOPE * v0.w);
            h.b.x = fmaxf(v1.x, NEG_SLOPE * v1.x);
            h.b.y = fmaxf(v1.y, NEG_SLOPE * v1.y);
            h.b.z = fmaxf(v1.z, NEG_SLOPE * v1.z);
            h.b.w = fmaxf(v1.w, NEG_SLOPE * v1.w);

            stg256_cs(op + off, h);
        }
    }
}

extern "C" void kernel_launch(void* const* d_in, const int* in_sizes, int n_in,
                              void* d_out, int out_size)
{
    const float* x    = (const float*)d_in[0];  // (B=1, T, Z, H, W)
    const float* w_ih = (const float*)d_in[1];  // (Z, H, W)
    const float* w_hh = (const float*)d_in[2];
    const float* b_hh = (const float*)d_in[3];
    float* out = (float*)d_out;

    int P = in_sizes[1];            // Z*H*W = 2097152
    int T = in_sizes[0] / P;        // 50
    int P8 = P / 8;                 // 262144

    int threads = 256;
    int nblocks = P8 / threads / 2; // 512 CTAs, 2 chunks each, single wave
    pixelwise_rnn_kernel<<<nblocks, threads>>>(
        (const f8*)x, (const f8*)w_ih, (const f8*)w_hh,
        (const f8*)b_hh, (f8*)out, P8, T, nblocks);
}